// round 11
// baseline (speedup 1.0000x reference)
#include <cuda_runtime.h>
#include <cstdint>

// Problem constants (fixed by the reference)
#define NB 4
#define NN 10000
#define NE 160000
#define HH 128
#define FF 32
#define MM 256
#define BN (NB * NN)          // 40000 node rows total

// Expected element counts (for input identification)
#define SZ_HIDDEN (NB * NN * HH)        // 5,120,000
#define SZ_EF     (NB * NE * FF)        // 20,480,000
#define SZ_IDX    (NB * NE)             // 640,000
#define SZ_W      ((FF + 2 * HH) * MM)  // 73,728
#define SZ_B      (MM)                  // 256

// Scratch
__device__ float g_Ps[(size_t)BN * MM];
__device__ float g_Pt[(size_t)BN * MM];
__device__ int g_srcg[SZ_IDX];   // global src row per edge
__device__ int g_tgtg[SZ_IDX];   // global tgt row per edge
__device__ int g_eid[SZ_IDX];    // edge ids in CSR order
__device__ int g_deg[BN];
__device__ int g_start[BN + 1];
__device__ int g_cursor[BN];
__device__ int g_is64[2];

// ---------------------------------------------------------------------------
// Index dtype detection (reads only first 512 B — in-bounds for i32 or i64).
// ---------------------------------------------------------------------------
__global__ void detect_idx_kernel(const int* __restrict__ raw_a,
                                  const int* __restrict__ raw_b) {
    if (threadIdx.x == 0 && blockIdx.x == 0) {
        int oa = 0, ob = 0;
#pragma unroll
        for (int j = 1; j < 128; j += 2) { oa |= raw_a[j]; ob |= raw_b[j]; }
        g_is64[0] = (oa == 0) ? 1 : 0;
        g_is64[1] = (ob == 0) ? 1 : 0;
    }
}

__global__ void zero_deg_kernel() {
    int i = blockIdx.x * blockDim.x + threadIdx.x;
    if (i < BN) g_deg[i] = 0;
}

// ---------------------------------------------------------------------------
// Normalize indices to global rows + histogram of targets.
// ---------------------------------------------------------------------------
__global__ void histo_kernel(const void* __restrict__ raw_src,
                             const void* __restrict__ raw_tgt) {
    int i = blockIdx.x * blockDim.x + threadIdx.x;
    if (i >= SZ_IDX) return;
    int b = i / NE;
    int sv, tv;
    if (g_is64[0]) sv = (int)((const long long*)raw_src)[i];
    else           sv = ((const int*)raw_src)[i];
    if (g_is64[1]) tv = (int)((const long long*)raw_tgt)[i];
    else           tv = ((const int*)raw_tgt)[i];
    sv = (sv < 0) ? 0 : (sv >= NN ? NN - 1 : sv);
    tv = (tv < 0) ? 0 : (tv >= NN ? NN - 1 : tv);
    int tg = b * NN + tv;
    g_srcg[i] = b * NN + sv;
    g_tgtg[i] = tg;
    atomicAdd(&g_deg[tg], 1);
}

// ---------------------------------------------------------------------------
// Single-block exclusive scan of g_deg -> g_start / g_cursor.
// ---------------------------------------------------------------------------
#define SCAN_T 1024
#define CHUNK ((BN + SCAN_T - 1) / SCAN_T)   // 40
__global__ __launch_bounds__(SCAN_T) void scan_kernel() {
    __shared__ int sm[SCAN_T];
    int tid = threadIdx.x;
    int base = tid * CHUNK;
    int s = 0;
#pragma unroll 4
    for (int i = 0; i < CHUNK; i++) {
        int n = base + i;
        if (n < BN) s += g_deg[n];
    }
    int incl = s;
    sm[tid] = incl;
    __syncthreads();
    for (int off = 1; off < SCAN_T; off <<= 1) {
        int u = (tid >= off) ? sm[tid - off] : 0;
        __syncthreads();
        incl += u;
        sm[tid] = incl;
        __syncthreads();
    }
    int run = incl - s;  // exclusive prefix for this chunk
    for (int i = 0; i < CHUNK; i++) {
        int n = base + i;
        if (n < BN) {
            g_start[n] = run;
            g_cursor[n] = run;
            run += g_deg[n];
        }
    }
    if (tid == SCAN_T - 1) g_start[BN] = incl;
}

// ---------------------------------------------------------------------------
// Scatter edge ids into CSR order (atomic cursor).
// ---------------------------------------------------------------------------
__global__ void scatter_kernel() {
    int i = blockIdx.x * blockDim.x + threadIdx.x;
    if (i >= SZ_IDX) return;
    int pos = atomicAdd(&g_cursor[g_tgtg[i]], 1);
    g_eid[pos] = i;
}

// ---------------------------------------------------------------------------
// Fused node projection GEMM: Ps and Pt share the A tile.
// ---------------------------------------------------------------------------
__global__ __launch_bounds__(256) void node_proj_kernel(
    const float* __restrict__ X,
    const float* __restrict__ Ws,
    const float* __restrict__ Wt,
    const float* __restrict__ bias)
{
    __shared__ float As[16][64];
    __shared__ float Bs[16][64];
    __shared__ float Cs[16][64];

    const int rblk = blockIdx.x * 64;
    const int cblk = blockIdx.y * 64;
    const int t  = threadIdx.x;
    const int tx = t & 15;
    const int ty = t >> 4;

    float accB[4][4], accC[4][4];
#pragma unroll
    for (int i = 0; i < 4; i++)
#pragma unroll
        for (int j = 0; j < 4; j++) { accB[i][j] = 0.f; accC[i][j] = 0.f; }

    const int lr = t >> 2;
    const int lk = (t & 3) * 4;
    const int bk = t >> 4;
    const int bm = (t & 15) * 4;

#pragma unroll 1
    for (int k0 = 0; k0 < HH; k0 += 16) {
        float4 av = *(const float4*)&X[(size_t)(rblk + lr) * HH + k0 + lk];
        float4 bv = *(const float4*)&Ws[(size_t)(k0 + bk) * MM + cblk + bm];
        float4 cv = *(const float4*)&Wt[(size_t)(k0 + bk) * MM + cblk + bm];
        __syncthreads();
        As[lk + 0][lr] = av.x; As[lk + 1][lr] = av.y;
        As[lk + 2][lr] = av.z; As[lk + 3][lr] = av.w;
        *(float4*)&Bs[bk][bm] = bv;
        *(float4*)&Cs[bk][bm] = cv;
        __syncthreads();

#pragma unroll
        for (int k = 0; k < 16; k++) {
            float4 a = *(const float4*)&As[k][ty * 4];
            float4 b = *(const float4*)&Bs[k][tx * 4];
            float4 c = *(const float4*)&Cs[k][tx * 4];
            accB[0][0] += a.x * b.x; accB[0][1] += a.x * b.y; accB[0][2] += a.x * b.z; accB[0][3] += a.x * b.w;
            accB[1][0] += a.y * b.x; accB[1][1] += a.y * b.y; accB[1][2] += a.y * b.z; accB[1][3] += a.y * b.w;
            accB[2][0] += a.z * b.x; accB[2][1] += a.z * b.y; accB[2][2] += a.z * b.z; accB[2][3] += a.z * b.w;
            accB[3][0] += a.w * b.x; accB[3][1] += a.w * b.y; accB[3][2] += a.w * b.z; accB[3][3] += a.w * b.w;
            accC[0][0] += a.x * c.x; accC[0][1] += a.x * c.y; accC[0][2] += a.x * c.z; accC[0][3] += a.x * c.w;
            accC[1][0] += a.y * c.x; accC[1][1] += a.y * c.y; accC[1][2] += a.y * c.z; accC[1][3] += a.y * c.w;
            accC[2][0] += a.z * c.x; accC[2][1] += a.z * c.y; accC[2][2] += a.z * c.z; accC[2][3] += a.z * c.w;
            accC[3][0] += a.w * c.x; accC[3][1] += a.w * c.y; accC[3][2] += a.w * c.z; accC[3][3] += a.w * c.w;
        }
    }

    float4 bvv = *(const float4*)&bias[cblk + tx * 4];

#pragma unroll
    for (int i = 0; i < 4; i++) {
        int row = rblk + ty * 4 + i;
        float4 o1, o2;
        o1.x = accB[i][0]; o1.y = accB[i][1]; o1.z = accB[i][2]; o1.w = accB[i][3];
        o2.x = accC[i][0] + bvv.x;
        o2.y = accC[i][1] + bvv.y;
        o2.z = accC[i][2] + bvv.z;
        o2.w = accC[i][3] + bvv.w;
        *(float4*)&g_Ps[(size_t)row * MM + cblk + tx * 4] = o1;
        *(float4*)&g_Pt[(size_t)row * MM + cblk + tx * 4] = o2;
    }
}

// ---------------------------------------------------------------------------
// CSR aggregation kernel: one WARP per node, 8 warps per block.
// Lane owns cols c0=lane*4 and c1=c0+128 (8 cols). Edges processed in octets:
// inner k-step = 4 LDS.128 + 64 FFMA (1.0 B/FMA, LDS/FMA balance point).
// Pt loaded once per node. Output written with plain stores (no atomics,
// covers every element -> no zero kernel needed).
// ---------------------------------------------------------------------------
__global__ __launch_bounds__(256) void agg_kernel(
    const float* __restrict__ ef,   // [NB*NE, 32]
    const float* __restrict__ W,    // first 32 rows of W_msg, row stride 256
    float* __restrict__ out)        // [BN, 256]
{
    __shared__ float Wf[FF][MM];          // 32 KB
    __shared__ float efsA[8][FF][4];      // 4 KB  edges 0-3 of octet, [warp][k][e]
    __shared__ float efsB[8][FF][4];      // 4 KB  edges 4-7

    const int t = threadIdx.x;
    // Stage Wf
    {
        float4* wsh = (float4*)&Wf[0][0];
        const float4* wg = (const float4*)W;
#pragma unroll
        for (int i = 0; i < 8; i++) wsh[t + 256 * i] = wg[t + 256 * i];
    }
    __syncthreads();

    const int warp = t >> 5;
    const int lane = t & 31;
    const int n = blockIdx.x * 8 + warp;          // grid = BN/8
    const int beg = g_start[n];
    const int end = g_start[n + 1];
    const int c0 = lane * 4;
    const int c1 = c0 + 128;

    float4 pt0 = *(const float4*)&g_Pt[(size_t)n * MM + c0];
    float4 pt1 = *(const float4*)&g_Pt[(size_t)n * MM + c1];
    float4 acc0 = make_float4(0.f, 0.f, 0.f, 0.f);
    float4 acc1 = acc0;

    const int sj = lane >> 3;           // staging: edge-within-half 0..3
    const int sc = (lane & 7) * 4;      // staging: feature quad

    for (int q = beg; q < end; q += 8) {
        const int cnt = min(8, end - q);

        // Stage up to 8 ef rows, transposed ([k][edge]); dup edge 0 for tails.
#pragma unroll
        for (int it = 0; it < 2; it++) {
            int j = sj + it * 4;                       // 0..7
            int jj = (j < cnt) ? j : 0;
            int e = g_eid[q + jj];
            float4 v = *(const float4*)&ef[(size_t)e * FF + sc];
            if (it == 0) {
                efsA[warp][sc + 0][sj] = v.x; efsA[warp][sc + 1][sj] = v.y;
                efsA[warp][sc + 2][sj] = v.z; efsA[warp][sc + 3][sj] = v.w;
            } else {
                efsB[warp][sc + 0][sj] = v.x; efsB[warp][sc + 1][sj] = v.y;
                efsB[warp][sc + 2][sj] = v.z; efsB[warp][sc + 3][sj] = v.w;
            }
        }
        __syncwarp();

        // 8 edges x 8 cols GEMM
        float4 mA[8], mB[8];
#pragma unroll
        for (int j = 0; j < 8; j++) {
            mA[j] = make_float4(0.f, 0.f, 0.f, 0.f);
            mB[j] = mA[j];
        }
#pragma unroll
        for (int k = 0; k < FF; k++) {
            float4 aA = *(const float4*)&efsA[warp][k][0];
            float4 aB = *(const float4*)&efsB[warp][k][0];
            float4 w0 = *(const float4*)&Wf[k][c0];
            float4 w1 = *(const float4*)&Wf[k][c1];
            float a[8] = {aA.x, aA.y, aA.z, aA.w, aB.x, aB.y, aB.z, aB.w};
#pragma unroll
            for (int j = 0; j < 8; j++) {
                mA[j].x += a[j] * w0.x; mA[j].y += a[j] * w0.y;
                mA[j].z += a[j] * w0.z; mA[j].w += a[j] * w0.w;
                mB[j].x += a[j] * w1.x; mB[j].y += a[j] * w1.y;
                mB[j].z += a[j] * w1.z; mB[j].w += a[j] * w1.w;
            }
        }

        // Epilogue: gather Ps[src], relu, accumulate into node acc
#pragma unroll
        for (int j = 0; j < 8; j++) {
            if (j < cnt) {
                int e = g_eid[q + j];
                int s = g_srcg[e];
                float4 ps0 = *(const float4*)&g_Ps[(size_t)s * MM + c0];
                float4 ps1 = *(const float4*)&g_Ps[(size_t)s * MM + c1];
                acc0.x += fmaxf(mA[j].x + ps0.x + pt0.x, 0.f);
                acc0.y += fmaxf(mA[j].y + ps0.y + pt0.y, 0.f);
                acc0.z += fmaxf(mA[j].z + ps0.z + pt0.z, 0.f);
                acc0.w += fmaxf(mA[j].w + ps0.w + pt0.w, 0.f);
                acc1.x += fmaxf(mB[j].x + ps1.x + pt1.x, 0.f);
                acc1.y += fmaxf(mB[j].y + ps1.y + pt1.y, 0.f);
                acc1.z += fmaxf(mB[j].z + ps1.z + pt1.z, 0.f);
                acc1.w += fmaxf(mB[j].w + ps1.w + pt1.w, 0.f);
            }
        }
        __syncwarp();
    }

    *(float4*)&out[(size_t)n * MM + c0] = acc0;
    *(float4*)&out[(size_t)n * MM + c1] = acc1;
}

// ---------------------------------------------------------------------------
// kernel_launch — inputs identified BY ELEMENT COUNT; index dtype detected
// on device. Output [4,10000,256] fully written by agg_kernel.
// ---------------------------------------------------------------------------
extern "C" void kernel_launch(void* const* d_in, const int* in_sizes, int n_in,
                              void* d_out, int out_size) {
    const float* hidden = nullptr;
    const float* ef     = nullptr;
    const void*  srcs   = nullptr;
    const void*  tgts   = nullptr;
    const float* W      = nullptr;
    const float* bmsg   = nullptr;

    for (int i = 0; i < n_in; i++) {
        switch (in_sizes[i]) {
            case SZ_HIDDEN: hidden = (const float*)d_in[i]; break;
            case SZ_EF:     ef     = (const float*)d_in[i]; break;
            case SZ_W:      W      = (const float*)d_in[i]; break;
            case SZ_B:      bmsg   = (const float*)d_in[i]; break;
            case SZ_IDX:
                if (!srcs) srcs = d_in[i];
                else       tgts = d_in[i];
                break;
            default: break;
        }
    }
    float* out = (float*)d_out;

    // 0) CSR build: detect dtype, histogram targets, scan, scatter
    detect_idx_kernel<<<1, 32>>>((const int*)srcs, (const int*)tgts);
    zero_deg_kernel<<<(BN + 255) / 256, 256>>>();
    histo_kernel<<<(SZ_IDX + 255) / 256, 256>>>(srcs, tgts);
    scan_kernel<<<1, SCAN_T>>>();
    scatter_kernel<<<(SZ_IDX + 255) / 256, 256>>>();

    // 1) fused node projections: Ps = h @ W[32:160], Pt = h @ W[160:288] + b
    dim3 gA(BN / 64, MM / 64);
    node_proj_kernel<<<gA, 256>>>(hidden,
                                  W + (size_t)FF * MM,
                                  W + (size_t)(FF + HH) * MM,
                                  bmsg);

    // 2) CSR aggregation (messages + relu + per-node sum, plain stores)
    agg_kernel<<<BN / 8, 256>>>(ef, W, out);
}

// round 12
// speedup vs baseline: 1.3888x; 1.3888x over previous
#include <cuda_runtime.h>
#include <cstdint>

// Problem constants (fixed by the reference)
#define NB 4
#define NN 10000
#define NE 160000
#define HH 128
#define FF 32
#define MM 256
#define BN (NB * NN)
#define EBLK 64
#define BLOCKS_PER_BATCH (NE / EBLK)  // 2500

// Expected element counts (for input identification)
#define SZ_HIDDEN (NB * NN * HH)        // 5,120,000
#define SZ_EF     (NB * NE * FF)        // 20,480,000
#define SZ_IDX    (NB * NE)             // 640,000
#define SZ_W      ((FF + 2 * HH) * MM)  // 73,728
#define SZ_B      (MM)                  // 256

// Scratch
__device__ float g_Ps[(size_t)BN * MM];
__device__ float g_Pt[(size_t)BN * MM];
__device__ int g_src[SZ_IDX];
__device__ int g_tgt[SZ_IDX];
__device__ int g_is64[2];

// ---------------------------------------------------------------------------
// Zero the (poisoned) output buffer.
// ---------------------------------------------------------------------------
__global__ void zero_kernel(float4* __restrict__ out, int n4) {
    int i = blockIdx.x * blockDim.x + threadIdx.x;
    if (i < n4) out[i] = make_float4(0.f, 0.f, 0.f, 0.f);
}

// ---------------------------------------------------------------------------
// Index dtype detection (reads only first 512 B — in-bounds for i32 or i64).
// ---------------------------------------------------------------------------
__global__ void detect_idx_kernel(const int* __restrict__ raw_a,
                                  const int* __restrict__ raw_b) {
    if (threadIdx.x == 0 && blockIdx.x == 0) {
        int oa = 0, ob = 0;
#pragma unroll
        for (int j = 1; j < 128; j += 2) { oa |= raw_a[j]; ob |= raw_b[j]; }
        g_is64[0] = (oa == 0) ? 1 : 0;
        g_is64[1] = (ob == 0) ? 1 : 0;
    }
}

// ---------------------------------------------------------------------------
// Normalize BOTH index arrays to int32 scratch (single launch), clamped.
// ---------------------------------------------------------------------------
__global__ void convert_idx_kernel(const void* __restrict__ raw_src,
                                   const void* __restrict__ raw_tgt) {
    int i = blockIdx.x * blockDim.x + threadIdx.x;
    if (i >= 2 * SZ_IDX) return;
    int which = (i >= SZ_IDX) ? 1 : 0;
    int j = i - which * SZ_IDX;
    const void* raw = which ? raw_tgt : raw_src;
    int v;
    if (g_is64[which]) v = (int)((const long long*)raw)[j];
    else               v = ((const int*)raw)[j];
    v = (v < 0) ? 0 : (v >= NN ? NN - 1 : v);
    if (which == 0) g_src[j] = v; else g_tgt[j] = v;
}

// ---------------------------------------------------------------------------
// Fused node projection GEMM: Ps = X@Ws, Pt = X@Wt + bias, sharing the A tile.
// Tile: 64 rows x 64 cols, 128 threads, microtile 8 rows x 4 cols (x2 mats).
// Inner k: 4 LDS.128 -> 128 lane-FMAs (0.5 B/FMA).
// ---------------------------------------------------------------------------
__global__ __launch_bounds__(128) void node_proj_kernel(
    const float* __restrict__ X,
    const float* __restrict__ Ws,
    const float* __restrict__ Wt,
    const float* __restrict__ bias)
{
    __shared__ float As[16][64];   // [k][row]
    __shared__ float Bs[16][64];   // [k][col] Ws
    __shared__ float Cs[16][64];   // [k][col] Wt

    const int rblk = blockIdx.x * 64;
    const int cblk = blockIdx.y * 64;
    const int t  = threadIdx.x;
    const int tx = t & 15;         // col quad (4 cols)
    const int ty = t >> 4;         // row octet (8 rows)

    float4 accB[8], accC[8];
#pragma unroll
    for (int r = 0; r < 8; r++) {
        accB[r] = make_float4(0.f, 0.f, 0.f, 0.f);
        accC[r] = accB[r];
    }

#pragma unroll 1
    for (int k0 = 0; k0 < HH; k0 += 16) {
        // Stage A: 64 rows x 16 k = 256 float4; 2 per thread
        float4 av0, av1, bv0, bv1, cv0, cv1;
        {
            int i0 = t, i1 = t + 128;
            int r0 = i0 >> 2, kq0 = (i0 & 3) * 4;
            int r1 = i1 >> 2, kq1 = (i1 & 3) * 4;
            av0 = *(const float4*)&X[(size_t)(rblk + r0) * HH + k0 + kq0];
            av1 = *(const float4*)&X[(size_t)(rblk + r1) * HH + k0 + kq1];
            int kr0 = i0 >> 4, cq0 = (i0 & 15) * 4;
            int kr1 = i1 >> 4, cq1 = (i1 & 15) * 4;
            bv0 = *(const float4*)&Ws[(size_t)(k0 + kr0) * MM + cblk + cq0];
            bv1 = *(const float4*)&Ws[(size_t)(k0 + kr1) * MM + cblk + cq1];
            cv0 = *(const float4*)&Wt[(size_t)(k0 + kr0) * MM + cblk + cq0];
            cv1 = *(const float4*)&Wt[(size_t)(k0 + kr1) * MM + cblk + cq1];
            __syncthreads();
            As[kq0 + 0][r0] = av0.x; As[kq0 + 1][r0] = av0.y;
            As[kq0 + 2][r0] = av0.z; As[kq0 + 3][r0] = av0.w;
            As[kq1 + 0][r1] = av1.x; As[kq1 + 1][r1] = av1.y;
            As[kq1 + 2][r1] = av1.z; As[kq1 + 3][r1] = av1.w;
            *(float4*)&Bs[kr0][cq0] = bv0;
            *(float4*)&Bs[kr1][cq1] = bv1;
            *(float4*)&Cs[kr0][cq0] = cv0;
            *(float4*)&Cs[kr1][cq1] = cv1;
            __syncthreads();
        }

#pragma unroll
        for (int k = 0; k < 16; k++) {
            float4 a0 = *(const float4*)&As[k][ty * 8];
            float4 a1 = *(const float4*)&As[k][ty * 8 + 4];
            float4 b  = *(const float4*)&Bs[k][tx * 4];
            float4 c  = *(const float4*)&Cs[k][tx * 4];
            float ar[8] = {a0.x, a0.y, a0.z, a0.w, a1.x, a1.y, a1.z, a1.w};
#pragma unroll
            for (int r = 0; r < 8; r++) {
                accB[r].x += ar[r] * b.x; accB[r].y += ar[r] * b.y;
                accB[r].z += ar[r] * b.z; accB[r].w += ar[r] * b.w;
                accC[r].x += ar[r] * c.x; accC[r].y += ar[r] * c.y;
                accC[r].z += ar[r] * c.z; accC[r].w += ar[r] * c.w;
            }
        }
    }

    float4 bvv = *(const float4*)&bias[cblk + tx * 4];

#pragma unroll
    for (int r = 0; r < 8; r++) {
        int row = rblk + ty * 8 + r;
        float4 o2;
        o2.x = accC[r].x + bvv.x;
        o2.y = accC[r].y + bvv.y;
        o2.z = accC[r].z + bvv.z;
        o2.w = accC[r].w + bvv.w;
        *(float4*)&g_Ps[(size_t)row * MM + cblk + tx * 4] = accB[r];
        *(float4*)&g_Pt[(size_t)row * MM + cblk + tx * 4] = o2;
    }
}

// ---------------------------------------------------------------------------
// Edge kernel: 64 contiguous edges per block, 256 threads = 8 warps.
// Warp w owns edge octet w (8 edges); lane owns cols c0=lane*4, c1=c0+128.
// Per thread: 8 edges x 8 cols; inner k = 4 LDS.128 (2 broadcast) + 64 FMA.
// Single pass (no octet loop). Epilogue: gathers + relu + red.v4 scatter.
// ---------------------------------------------------------------------------
__global__ __launch_bounds__(256) void edge_kernel(
    const float* __restrict__ ef,   // [NB*NE, 32]
    const float* __restrict__ W,    // first 32 rows of W_msg, row stride 256
    float* __restrict__ out)        // [BN, 256]
{
    __shared__ float Wf[FF][MM];            // 32 KB
    __shared__ float efs_t[FF][EBLK + 8];   // [k][edge], row stride 288B (16B-aligned)
    __shared__ int   src_s[EBLK];
    __shared__ int   tgt_s[EBLK];

    const int t   = threadIdx.x;
    const int blk = blockIdx.x;
    const int b   = blk / BLOCKS_PER_BATCH;
    const int e0  = (blk % BLOCKS_PER_BATCH) * EBLK;
    const int ebase = b * NE + e0;

    // Stage Wf (2048 float4)
    {
        float4* wsh = (float4*)&Wf[0][0];
        const float4* wg = (const float4*)W;
#pragma unroll
        for (int i = 0; i < 8; i++) wsh[t + 256 * i] = wg[t + 256 * i];
    }
    // Stage edge features transposed: efs_t[k][edge]
    {
#pragma unroll
        for (int it = 0; it < 2; it++) {
            int i = t + 256 * it;
            int r = i >> 3;          // edge 0..63
            int c = (i & 7) * 4;     // feature quad
            float4 v = *(const float4*)&ef[(size_t)(ebase + r) * FF + c];
            efs_t[c + 0][r] = v.x; efs_t[c + 1][r] = v.y;
            efs_t[c + 2][r] = v.z; efs_t[c + 3][r] = v.w;
        }
    }
    if (t < EBLK) {
        src_s[t] = g_src[ebase + t];
        tgt_s[t] = g_tgt[ebase + t];
    }
    __syncthreads();

    const int warp = t >> 5;         // edge octet
    const int lane = t & 31;
    const int c0 = lane * 4;
    const int c1 = c0 + 128;
    const int nodebase = b * NN;

    float4 mA[8], mB[8];
#pragma unroll
    for (int j = 0; j < 8; j++) {
        mA[j] = make_float4(0.f, 0.f, 0.f, 0.f);
        mB[j] = mA[j];
    }

#pragma unroll 8
    for (int k = 0; k < FF; k++) {
        float4 aA = *(const float4*)&efs_t[k][warp * 8];      // edges 0-3 (broadcast)
        float4 aB = *(const float4*)&efs_t[k][warp * 8 + 4];  // edges 4-7 (broadcast)
        float4 w0 = *(const float4*)&Wf[k][c0];
        float4 w1 = *(const float4*)&Wf[k][c1];
        float a[8] = {aA.x, aA.y, aA.z, aA.w, aB.x, aB.y, aB.z, aB.w};
#pragma unroll
        for (int j = 0; j < 8; j++) {
            mA[j].x += a[j] * w0.x; mA[j].y += a[j] * w0.y;
            mA[j].z += a[j] * w0.z; mA[j].w += a[j] * w0.w;
            mB[j].x += a[j] * w1.x; mB[j].y += a[j] * w1.y;
            mB[j].z += a[j] * w1.z; mB[j].w += a[j] * w1.w;
        }
    }

    // Epilogue: per edge, gather Ps[src]/Pt[tgt], relu, vector reduction
#pragma unroll
    for (int j = 0; j < 8; j++) {
        const int e = warp * 8 + j;
        const int s = nodebase + src_s[e];
        const int d = nodebase + tgt_s[e];

        float4 ps0 = *(const float4*)&g_Ps[(size_t)s * MM + c0];
        float4 pt0 = *(const float4*)&g_Pt[(size_t)d * MM + c0];
        float4 r0;
        r0.x = fmaxf(mA[j].x + ps0.x + pt0.x, 0.f);
        r0.y = fmaxf(mA[j].y + ps0.y + pt0.y, 0.f);
        r0.z = fmaxf(mA[j].z + ps0.z + pt0.z, 0.f);
        r0.w = fmaxf(mA[j].w + ps0.w + pt0.w, 0.f);
        float* op0 = &out[(size_t)d * MM + c0];
        asm volatile("red.global.add.v4.f32 [%0], {%1, %2, %3, %4};"
                     :: "l"(op0), "f"(r0.x), "f"(r0.y), "f"(r0.z), "f"(r0.w)
                     : "memory");

        float4 ps1 = *(const float4*)&g_Ps[(size_t)s * MM + c1];
        float4 pt1 = *(const float4*)&g_Pt[(size_t)d * MM + c1];
        float4 r1;
        r1.x = fmaxf(mB[j].x + ps1.x + pt1.x, 0.f);
        r1.y = fmaxf(mB[j].y + ps1.y + pt1.y, 0.f);
        r1.z = fmaxf(mB[j].z + ps1.z + pt1.z, 0.f);
        r1.w = fmaxf(mB[j].w + ps1.w + pt1.w, 0.f);
        float* op1 = &out[(size_t)d * MM + c1];
        asm volatile("red.global.add.v4.f32 [%0], {%1, %2, %3, %4};"
                     :: "l"(op1), "f"(r1.x), "f"(r1.y), "f"(r1.z), "f"(r1.w)
                     : "memory");
    }
}

// ---------------------------------------------------------------------------
// kernel_launch — inputs identified BY ELEMENT COUNT; index dtype detected
// on device. Output f32 [4,10000,256].
// ---------------------------------------------------------------------------
extern "C" void kernel_launch(void* const* d_in, const int* in_sizes, int n_in,
                              void* d_out, int out_size) {
    const float* hidden = nullptr;
    const float* ef     = nullptr;
    const void*  srcs   = nullptr;
    const void*  tgts   = nullptr;
    const float* W      = nullptr;
    const float* bmsg   = nullptr;

    for (int i = 0; i < n_in; i++) {
        switch (in_sizes[i]) {
            case SZ_HIDDEN: hidden = (const float*)d_in[i]; break;
            case SZ_EF:     ef     = (const float*)d_in[i]; break;
            case SZ_W:      W      = (const float*)d_in[i]; break;
            case SZ_B:      bmsg   = (const float*)d_in[i]; break;
            case SZ_IDX:
                if (!srcs) srcs = d_in[i];
                else       tgts = d_in[i];
                break;
            default: break;
        }
    }
    float* out = (float*)d_out;

    // 0) detect index dtype + normalize to int32 scratch
    detect_idx_kernel<<<1, 32>>>((const int*)srcs, (const int*)tgts);
    convert_idx_kernel<<<(2 * SZ_IDX + 255) / 256, 256>>>(srcs, tgts);

    // 1) zero output (poisoned by harness)
    int n4 = out_size / 4;
    zero_kernel<<<(n4 + 255) / 256, 256>>>((float4*)out, n4);

    // 2) fused node projections: Ps = h @ W[32:160], Pt = h @ W[160:288] + b
    dim3 gA(BN / 64, MM / 64);
    node_proj_kernel<<<gA, 128>>>(hidden,
                                  W + (size_t)FF * MM,
                                  W + (size_t)(FF + HH) * MM,
                                  bmsg);

    // 3) per-edge message + scatter-add (8 edges x 8 cols per thread)
    edge_kernel<<<NB * BLOCKS_PER_BATCH, 256>>>(ef, W, out);
}

// round 14
// speedup vs baseline: 1.5853x; 1.1415x over previous
#include <cuda_runtime.h>
#include <cstdint>

// Problem constants (fixed by the reference)
#define NB 4
#define NN 10000
#define NE 160000
#define HH 128
#define FF 32
#define MM 256
#define BN (NB * NN)
#define EBLK 64
#define BLOCKS_PER_BATCH (NE / EBLK)  // 2500

// Expected element counts (for input identification)
#define SZ_HIDDEN (NB * NN * HH)        // 5,120,000
#define SZ_EF     (NB * NE * FF)        // 20,480,000
#define SZ_IDX    (NB * NE)             // 640,000
#define SZ_W      ((FF + 2 * HH) * MM)  // 73,728
#define SZ_B      (MM)                  // 256

// Scratch
__device__ float g_Ps[(size_t)BN * MM];
__device__ float g_Pt[(size_t)BN * MM];
__device__ int g_src[SZ_IDX];
__device__ int g_tgt[SZ_IDX];
__device__ int g_is64[2];

// ---------------------------------------------------------------------------
// Zero the (poisoned) output buffer.
// ---------------------------------------------------------------------------
__global__ void zero_kernel(float4* __restrict__ out, int n4) {
    int i = blockIdx.x * blockDim.x + threadIdx.x;
    if (i < n4) out[i] = make_float4(0.f, 0.f, 0.f, 0.f);
}

// ---------------------------------------------------------------------------
// Index dtype detection (reads only first 512 B — in-bounds for i32 or i64).
// ---------------------------------------------------------------------------
__global__ void detect_idx_kernel(const int* __restrict__ raw_a,
                                  const int* __restrict__ raw_b) {
    if (threadIdx.x == 0 && blockIdx.x == 0) {
        int oa = 0, ob = 0;
#pragma unroll
        for (int j = 1; j < 128; j += 2) { oa |= raw_a[j]; ob |= raw_b[j]; }
        g_is64[0] = (oa == 0) ? 1 : 0;
        g_is64[1] = (ob == 0) ? 1 : 0;
    }
}

// ---------------------------------------------------------------------------
// Normalize BOTH index arrays to int32 scratch (single launch), clamped.
// ---------------------------------------------------------------------------
__global__ void convert_idx_kernel(const void* __restrict__ raw_src,
                                   const void* __restrict__ raw_tgt) {
    int i = blockIdx.x * blockDim.x + threadIdx.x;
    if (i >= 2 * SZ_IDX) return;
    int which = (i >= SZ_IDX) ? 1 : 0;
    int j = i - which * SZ_IDX;
    const void* raw = which ? raw_tgt : raw_src;
    int v;
    if (g_is64[which]) v = (int)((const long long*)raw)[j];
    else               v = ((const int*)raw)[j];
    v = (v < 0) ? 0 : (v >= NN ? NN - 1 : v);
    if (which == 0) g_src[j] = v; else g_tgt[j] = v;
}

// ---------------------------------------------------------------------------
// Fused node projection GEMM: Ps = X@Ws, Pt = X@Wt + bias, sharing the A tile.
// Tile: 64 rows x 64 cols, 128 threads, microtile 8 rows x 4 cols (x2 mats).
// ---------------------------------------------------------------------------
__global__ __launch_bounds__(128) void node_proj_kernel(
    const float* __restrict__ X,
    const float* __restrict__ Ws,
    const float* __restrict__ Wt,
    const float* __restrict__ bias)
{
    __shared__ float As[16][64];   // [k][row]
    __shared__ float Bs[16][64];   // [k][col] Ws
    __shared__ float Cs[16][64];   // [k][col] Wt

    const int rblk = blockIdx.x * 64;
    const int cblk = blockIdx.y * 64;
    const int t  = threadIdx.x;
    const int tx = t & 15;         // col quad (4 cols)
    const int ty = t >> 4;         // row octet (8 rows)

    float4 accB[8], accC[8];
#pragma unroll
    for (int r = 0; r < 8; r++) {
        accB[r] = make_float4(0.f, 0.f, 0.f, 0.f);
        accC[r] = accB[r];
    }

#pragma unroll 1
    for (int k0 = 0; k0 < HH; k0 += 16) {
        float4 av0, av1, bv0, bv1, cv0, cv1;
        {
            int i0 = t, i1 = t + 128;
            int r0 = i0 >> 2, kq0 = (i0 & 3) * 4;
            int r1 = i1 >> 2, kq1 = (i1 & 3) * 4;
            av0 = *(const float4*)&X[(size_t)(rblk + r0) * HH + k0 + kq0];
            av1 = *(const float4*)&X[(size_t)(rblk + r1) * HH + k0 + kq1];
            int kr0 = i0 >> 4, cq0 = (i0 & 15) * 4;
            int kr1 = i1 >> 4, cq1 = (i1 & 15) * 4;
            bv0 = *(const float4*)&Ws[(size_t)(k0 + kr0) * MM + cblk + cq0];
            bv1 = *(const float4*)&Ws[(size_t)(k0 + kr1) * MM + cblk + cq1];
            cv0 = *(const float4*)&Wt[(size_t)(k0 + kr0) * MM + cblk + cq0];
            cv1 = *(const float4*)&Wt[(size_t)(k0 + kr1) * MM + cblk + cq1];
            __syncthreads();
            As[kq0 + 0][r0] = av0.x; As[kq0 + 1][r0] = av0.y;
            As[kq0 + 2][r0] = av0.z; As[kq0 + 3][r0] = av0.w;
            As[kq1 + 0][r1] = av1.x; As[kq1 + 1][r1] = av1.y;
            As[kq1 + 2][r1] = av1.z; As[kq1 + 3][r1] = av1.w;
            *(float4*)&Bs[kr0][cq0] = bv0;
            *(float4*)&Bs[kr1][cq1] = bv1;
            *(float4*)&Cs[kr0][cq0] = cv0;
            *(float4*)&Cs[kr1][cq1] = cv1;
            __syncthreads();
        }

#pragma unroll
        for (int k = 0; k < 16; k++) {
            float4 a0 = *(const float4*)&As[k][ty * 8];
            float4 a1 = *(const float4*)&As[k][ty * 8 + 4];
            float4 b  = *(const float4*)&Bs[k][tx * 4];
            float4 c  = *(const float4*)&Cs[k][tx * 4];
            float ar[8] = {a0.x, a0.y, a0.z, a0.w, a1.x, a1.y, a1.z, a1.w};
#pragma unroll
            for (int r = 0; r < 8; r++) {
                accB[r].x += ar[r] * b.x; accB[r].y += ar[r] * b.y;
                accB[r].z += ar[r] * b.z; accB[r].w += ar[r] * b.w;
                accC[r].x += ar[r] * c.x; accC[r].y += ar[r] * c.y;
                accC[r].z += ar[r] * c.z; accC[r].w += ar[r] * c.w;
            }
        }
    }

    float4 bvv = *(const float4*)&bias[cblk + tx * 4];

#pragma unroll
    for (int r = 0; r < 8; r++) {
        int row = rblk + ty * 8 + r;
        float4 o2;
        o2.x = accC[r].x + bvv.x;
        o2.y = accC[r].y + bvv.y;
        o2.z = accC[r].z + bvv.z;
        o2.w = accC[r].w + bvv.w;
        *(float4*)&g_Ps[(size_t)row * MM + cblk + tx * 4] = accB[r];
        *(float4*)&g_Pt[(size_t)row * MM + cblk + tx * 4] = o2;
    }
}

// ---------------------------------------------------------------------------
// Edge kernel: 64 contiguous edges per block, 256 threads = 8 warps.
// Warp w owns edge octet w (8 edges); lane owns cols c0=lane*4, c1=c0+128.
// GEMM: 8 edges x 8 cols per thread; inner k = 4 LDS.128 (2 bcast) + 64 FMA.
// Epilogue is PHASE-SPLIT: all gathers (high MLP, no asm barriers between
// loads) -> relu into registers -> all red.v4 ops back-to-back. This removes
// the per-edge serialization the "memory" clobber forced in the fused form.
// ---------------------------------------------------------------------------
__global__ __launch_bounds__(256, 2) void edge_kernel(
    const float* __restrict__ ef,   // [NB*NE, 32]
    const float* __restrict__ W,    // first 32 rows of W_msg, row stride 256
    float* __restrict__ out)        // [BN, 256]
{
    __shared__ float Wf[FF][MM];            // 32 KB
    __shared__ float efs_t[FF][EBLK + 8];   // [k][edge]
    __shared__ int   src_s[EBLK];
    __shared__ int   tgt_s[EBLK];

    const int t   = threadIdx.x;
    const int blk = blockIdx.x;
    const int b   = blk / BLOCKS_PER_BATCH;
    const int e0  = (blk % BLOCKS_PER_BATCH) * EBLK;
    const int ebase = b * NE + e0;

    // Stage Wf (2048 float4)
    {
        float4* wsh = (float4*)&Wf[0][0];
        const float4* wg = (const float4*)W;
#pragma unroll
        for (int i = 0; i < 8; i++) wsh[t + 256 * i] = wg[t + 256 * i];
    }
    // Stage edge features transposed: efs_t[k][edge]
    {
#pragma unroll
        for (int it = 0; it < 2; it++) {
            int i = t + 256 * it;
            int r = i >> 3;
            int c = (i & 7) * 4;
            float4 v = *(const float4*)&ef[(size_t)(ebase + r) * FF + c];
            efs_t[c + 0][r] = v.x; efs_t[c + 1][r] = v.y;
            efs_t[c + 2][r] = v.z; efs_t[c + 3][r] = v.w;
        }
    }
    if (t < EBLK) {
        src_s[t] = g_src[ebase + t];
        tgt_s[t] = g_tgt[ebase + t];
    }
    __syncthreads();

    const int warp = t >> 5;
    const int lane = t & 31;
    const int c0 = lane * 4;
    const int c1 = c0 + 128;
    const int nodebase = b * NN;

    float4 mA[8], mB[8];
#pragma unroll
    for (int j = 0; j < 8; j++) {
        mA[j] = make_float4(0.f, 0.f, 0.f, 0.f);
        mB[j] = mA[j];
    }

#pragma unroll 8
    for (int k = 0; k < FF; k++) {
        float4 aA = *(const float4*)&efs_t[k][warp * 8];
        float4 aB = *(const float4*)&efs_t[k][warp * 8 + 4];
        float4 w0 = *(const float4*)&Wf[k][c0];
        float4 w1 = *(const float4*)&Wf[k][c1];
        float a[8] = {aA.x, aA.y, aA.z, aA.w, aB.x, aB.y, aB.z, aB.w};
#pragma unroll
        for (int j = 0; j < 8; j++) {
            mA[j].x += a[j] * w0.x; mA[j].y += a[j] * w0.y;
            mA[j].z += a[j] * w0.z; mA[j].w += a[j] * w0.w;
            mB[j].x += a[j] * w1.x; mB[j].y += a[j] * w1.y;
            mB[j].z += a[j] * w1.z; mB[j].w += a[j] * w1.w;
        }
    }

    // ---- Epilogue phase A: batched gathers + relu (no asm between loads) ----
    int sg[8], dg[8];
#pragma unroll
    for (int j = 0; j < 8; j++) {
        const int e = warp * 8 + j;
        sg[j] = nodebase + src_s[e];
        dg[j] = nodebase + tgt_s[e];
    }

#pragma unroll
    for (int j = 0; j < 8; j++) {
        float4 ps0 = *(const float4*)&g_Ps[(size_t)sg[j] * MM + c0];
        float4 pt0 = *(const float4*)&g_Pt[(size_t)dg[j] * MM + c0];
        mA[j].x = fmaxf(mA[j].x + ps0.x + pt0.x, 0.f);
        mA[j].y = fmaxf(mA[j].y + ps0.y + pt0.y, 0.f);
        mA[j].z = fmaxf(mA[j].z + ps0.z + pt0.z, 0.f);
        mA[j].w = fmaxf(mA[j].w + ps0.w + pt0.w, 0.f);
    }
#pragma unroll
    for (int j = 0; j < 8; j++) {
        float4 ps1 = *(const float4*)&g_Ps[(size_t)sg[j] * MM + c1];
        float4 pt1 = *(const float4*)&g_Pt[(size_t)dg[j] * MM + c1];
        mB[j].x = fmaxf(mB[j].x + ps1.x + pt1.x, 0.f);
        mB[j].y = fmaxf(mB[j].y + ps1.y + pt1.y, 0.f);
        mB[j].z = fmaxf(mB[j].z + ps1.z + pt1.z, 0.f);
        mB[j].w = fmaxf(mB[j].w + ps1.w + pt1.w, 0.f);
    }

    // ---- Epilogue phase B: back-to-back vector reductions ----
#pragma unroll
    for (int j = 0; j < 8; j++) {
        float* op0 = &out[(size_t)dg[j] * MM + c0];
        asm volatile("red.global.add.v4.f32 [%0], {%1, %2, %3, %4};"
                     :: "l"(op0), "f"(mA[j].x), "f"(mA[j].y), "f"(mA[j].z), "f"(mA[j].w)
                     : "memory");
    }
#pragma unroll
    for (int j = 0; j < 8; j++) {
        float* op1 = &out[(size_t)dg[j] * MM + c1];
        asm volatile("red.global.add.v4.f32 [%0], {%1, %2, %3, %4};"
                     :: "l"(op1), "f"(mB[j].x), "f"(mB[j].y), "f"(mB[j].z), "f"(mB[j].w)
                     : "memory");
    }
}

// ---------------------------------------------------------------------------
// kernel_launch — inputs identified BY ELEMENT COUNT; index dtype detected
// on device. Output f32 [4,10000,256].
// ---------------------------------------------------------------------------
extern "C" void kernel_launch(void* const* d_in, const int* in_sizes, int n_in,
                              void* d_out, int out_size) {
    const float* hidden = nullptr;
    const float* ef     = nullptr;
    const void*  srcs   = nullptr;
    const void*  tgts   = nullptr;
    const float* W      = nullptr;
    const float* bmsg   = nullptr;

    for (int i = 0; i < n_in; i++) {
        switch (in_sizes[i]) {
            case SZ_HIDDEN: hidden = (const float*)d_in[i]; break;
            case SZ_EF:     ef     = (const float*)d_in[i]; break;
            case SZ_W:      W      = (const float*)d_in[i]; break;
            case SZ_B:      bmsg   = (const float*)d_in[i]; break;
            case SZ_IDX:
                if (!srcs) srcs = d_in[i];
                else       tgts = d_in[i];
                break;
            default: break;
        }
    }
    float* out = (float*)d_out;

    // 0) detect index dtype + normalize to int32 scratch
    detect_idx_kernel<<<1, 32>>>((const int*)srcs, (const int*)tgts);
    convert_idx_kernel<<<(2 * SZ_IDX + 255) / 256, 256>>>(srcs, tgts);

    // 1) zero output (poisoned by harness)
    int n4 = out_size / 4;
    zero_kernel<<<(n4 + 255) / 256, 256>>>((float4*)out, n4);

    // 2) fused node projections: Ps = h @ W[32:160], Pt = h @ W[160:288] + b
    dim3 gA(BN / 64, MM / 64);
    node_proj_kernel<<<gA, 128>>>(hidden,
                                  W + (size_t)FF * MM,
                                  W + (size_t)(FF + HH) * MM,
                                  bmsg);

    // 3) per-edge message + scatter-add (phase-split epilogue)
    edge_kernel<<<NB * BLOCKS_PER_BATCH, 256>>>(ef, W, out);
}

// round 15
// speedup vs baseline: 1.7055x; 1.0758x over previous
#include <cuda_runtime.h>
#include <cstdint>

// Problem constants (fixed by the reference)
#define NB 4
#define NN 10000
#define NE 160000
#define HH 128
#define FF 32
#define MM 256
#define BN (NB * NN)
#define EBLK 64
#define BLOCKS_PER_BATCH (NE / EBLK)  // 2500

// Expected element counts (for input identification)
#define SZ_HIDDEN (NB * NN * HH)        // 5,120,000
#define SZ_EF     (NB * NE * FF)        // 20,480,000
#define SZ_IDX    (NB * NE)             // 640,000
#define SZ_W      ((FF + 2 * HH) * MM)  // 73,728
#define SZ_B      (MM)                  // 256

// Scratch
__device__ float g_Ps[(size_t)BN * MM];
__device__ float g_Pt[(size_t)BN * MM];
__device__ int g_src[SZ_IDX];
__device__ int g_tgt[SZ_IDX];
__device__ int g_is64[2];

// ---- packed f32x2 helpers (Blackwell sm_100+: 2x fp32 FMA rate) ----
__device__ __forceinline__ unsigned long long pack2(float x) {
    unsigned long long r;
    asm("mov.b64 %0, {%1, %1};" : "=l"(r) : "f"(x));
    return r;
}
__device__ __forceinline__ void unpack2(unsigned long long p, float& lo, float& hi) {
    asm("mov.b64 {%0, %1}, %2;" : "=f"(lo), "=f"(hi) : "l"(p));
}
#define FFMA2(d, a, b, c) \
    asm("fma.rn.f32x2 %0, %1, %2, %3;" : "=l"(d) : "l"(a), "l"(b), "l"(c))

// ---------------------------------------------------------------------------
// Zero the (poisoned) output buffer.
// ---------------------------------------------------------------------------
__global__ void zero_kernel(float4* __restrict__ out, int n4) {
    int i = blockIdx.x * blockDim.x + threadIdx.x;
    if (i < n4) out[i] = make_float4(0.f, 0.f, 0.f, 0.f);
}

// ---------------------------------------------------------------------------
// Index dtype detection (reads only first 512 B — in-bounds for i32 or i64).
// ---------------------------------------------------------------------------
__global__ void detect_idx_kernel(const int* __restrict__ raw_a,
                                  const int* __restrict__ raw_b) {
    if (threadIdx.x == 0 && blockIdx.x == 0) {
        int oa = 0, ob = 0;
#pragma unroll
        for (int j = 1; j < 128; j += 2) { oa |= raw_a[j]; ob |= raw_b[j]; }
        g_is64[0] = (oa == 0) ? 1 : 0;
        g_is64[1] = (ob == 0) ? 1 : 0;
    }
}

// ---------------------------------------------------------------------------
// Normalize BOTH index arrays to int32 scratch (single launch), clamped.
// ---------------------------------------------------------------------------
__global__ void convert_idx_kernel(const void* __restrict__ raw_src,
                                   const void* __restrict__ raw_tgt) {
    int i = blockIdx.x * blockDim.x + threadIdx.x;
    if (i >= 2 * SZ_IDX) return;
    int which = (i >= SZ_IDX) ? 1 : 0;
    int j = i - which * SZ_IDX;
    const void* raw = which ? raw_tgt : raw_src;
    int v;
    if (g_is64[which]) v = (int)((const long long*)raw)[j];
    else               v = ((const int*)raw)[j];
    v = (v < 0) ? 0 : (v >= NN ? NN - 1 : v);
    if (which == 0) g_src[j] = v; else g_tgt[j] = v;
}

// ---------------------------------------------------------------------------
// Fused node projection GEMM: Ps = X@Ws, Pt = X@Wt + bias, sharing the A tile.
// Tile: 64 rows x 64 cols, 128 threads, microtile 8 rows x 4 cols (x2 mats).
// Inner k uses packed f32x2 FMA: 8 packs + 32 FFMA2 (vs 64 scalar FFMA).
// ---------------------------------------------------------------------------
__global__ __launch_bounds__(128) void node_proj_kernel(
    const float* __restrict__ X,
    const float* __restrict__ Ws,
    const float* __restrict__ Wt,
    const float* __restrict__ bias)
{
    __shared__ float As[16][64];   // [k][row]
    __shared__ float Bs[16][64];   // [k][col] Ws
    __shared__ float Cs[16][64];   // [k][col] Wt

    const int rblk = blockIdx.x * 64;
    const int cblk = blockIdx.y * 64;
    const int t  = threadIdx.x;
    const int tx = t & 15;         // col quad (4 cols)
    const int ty = t >> 4;         // row octet (8 rows)

    unsigned long long accB2[8][2], accC2[8][2];
#pragma unroll
    for (int r = 0; r < 8; r++) {
        accB2[r][0] = 0ull; accB2[r][1] = 0ull;
        accC2[r][0] = 0ull; accC2[r][1] = 0ull;
    }

#pragma unroll 1
    for (int k0 = 0; k0 < HH; k0 += 16) {
        float4 av0, av1, bv0, bv1, cv0, cv1;
        {
            int i0 = t, i1 = t + 128;
            int r0 = i0 >> 2, kq0 = (i0 & 3) * 4;
            int r1 = i1 >> 2, kq1 = (i1 & 3) * 4;
            av0 = *(const float4*)&X[(size_t)(rblk + r0) * HH + k0 + kq0];
            av1 = *(const float4*)&X[(size_t)(rblk + r1) * HH + k0 + kq1];
            int kr0 = i0 >> 4, cq0 = (i0 & 15) * 4;
            int kr1 = i1 >> 4, cq1 = (i1 & 15) * 4;
            bv0 = *(const float4*)&Ws[(size_t)(k0 + kr0) * MM + cblk + cq0];
            bv1 = *(const float4*)&Ws[(size_t)(k0 + kr1) * MM + cblk + cq1];
            cv0 = *(const float4*)&Wt[(size_t)(k0 + kr0) * MM + cblk + cq0];
            cv1 = *(const float4*)&Wt[(size_t)(k0 + kr1) * MM + cblk + cq1];
            __syncthreads();
            As[kq0 + 0][r0] = av0.x; As[kq0 + 1][r0] = av0.y;
            As[kq0 + 2][r0] = av0.z; As[kq0 + 3][r0] = av0.w;
            As[kq1 + 0][r1] = av1.x; As[kq1 + 1][r1] = av1.y;
            As[kq1 + 2][r1] = av1.z; As[kq1 + 3][r1] = av1.w;
            *(float4*)&Bs[kr0][cq0] = bv0;
            *(float4*)&Bs[kr1][cq1] = bv1;
            *(float4*)&Cs[kr0][cq0] = cv0;
            *(float4*)&Cs[kr1][cq1] = cv1;
            __syncthreads();
        }

#pragma unroll
        for (int k = 0; k < 16; k++) {
            float4 a0 = *(const float4*)&As[k][ty * 8];
            float4 a1 = *(const float4*)&As[k][ty * 8 + 4];
            ulonglong2 b2 = *(const ulonglong2*)&Bs[k][tx * 4];
            ulonglong2 c2 = *(const ulonglong2*)&Cs[k][tx * 4];
            float ar[8] = {a0.x, a0.y, a0.z, a0.w, a1.x, a1.y, a1.z, a1.w};
#pragma unroll
            for (int r = 0; r < 8; r++) {
                unsigned long long ap = pack2(ar[r]);
                FFMA2(accB2[r][0], ap, b2.x, accB2[r][0]);
                FFMA2(accB2[r][1], ap, b2.y, accB2[r][1]);
                FFMA2(accC2[r][0], ap, c2.x, accC2[r][0]);
                FFMA2(accC2[r][1], ap, c2.y, accC2[r][1]);
            }
        }
    }

    float4 bvv = *(const float4*)&bias[cblk + tx * 4];

#pragma unroll
    for (int r = 0; r < 8; r++) {
        int row = rblk + ty * 8 + r;
        float4 o1, o2;
        unpack2(accB2[r][0], o1.x, o1.y);
        unpack2(accB2[r][1], o1.z, o1.w);
        unpack2(accC2[r][0], o2.x, o2.y);
        unpack2(accC2[r][1], o2.z, o2.w);
        o2.x += bvv.x; o2.y += bvv.y; o2.z += bvv.z; o2.w += bvv.w;
        *(float4*)&g_Ps[(size_t)row * MM + cblk + tx * 4] = o1;
        *(float4*)&g_Pt[(size_t)row * MM + cblk + tx * 4] = o2;
    }
}

// ---------------------------------------------------------------------------
// Edge kernel: 64 contiguous edges per block, 256 threads = 8 warps.
// Warp w owns edge octet w (8 edges); lane owns cols c0=lane*4, c1=c0+128.
// GEMM inner k uses packed f32x2: 8 packs + 32 FFMA2 (vs 64 scalar FFMA).
// Epilogue PHASE-SPLIT (R14 winner): batched gathers -> relu -> batched red.v4.
// ---------------------------------------------------------------------------
__global__ __launch_bounds__(256, 2) void edge_kernel(
    const float* __restrict__ ef,   // [NB*NE, 32]
    const float* __restrict__ W,    // first 32 rows of W_msg, row stride 256
    float* __restrict__ out)        // [BN, 256]
{
    __shared__ float Wf[FF][MM];            // 32 KB
    __shared__ float efs_t[FF][EBLK + 8];   // [k][edge]
    __shared__ int   src_s[EBLK];
    __shared__ int   tgt_s[EBLK];

    const int t   = threadIdx.x;
    const int blk = blockIdx.x;
    const int b   = blk / BLOCKS_PER_BATCH;
    const int e0  = (blk % BLOCKS_PER_BATCH) * EBLK;
    const int ebase = b * NE + e0;

    // Stage Wf (2048 float4)
    {
        float4* wsh = (float4*)&Wf[0][0];
        const float4* wg = (const float4*)W;
#pragma unroll
        for (int i = 0; i < 8; i++) wsh[t + 256 * i] = wg[t + 256 * i];
    }
    // Stage edge features transposed: efs_t[k][edge]
    {
#pragma unroll
        for (int it = 0; it < 2; it++) {
            int i = t + 256 * it;
            int r = i >> 3;
            int c = (i & 7) * 4;
            float4 v = *(const float4*)&ef[(size_t)(ebase + r) * FF + c];
            efs_t[c + 0][r] = v.x; efs_t[c + 1][r] = v.y;
            efs_t[c + 2][r] = v.z; efs_t[c + 3][r] = v.w;
        }
    }
    if (t < EBLK) {
        src_s[t] = g_src[ebase + t];
        tgt_s[t] = g_tgt[ebase + t];
    }
    __syncthreads();

    const int warp = t >> 5;
    const int lane = t & 31;
    const int c0 = lane * 4;
    const int c1 = c0 + 128;
    const int nodebase = b * NN;

    unsigned long long mA2[8][2], mB2[8][2];
#pragma unroll
    for (int j = 0; j < 8; j++) {
        mA2[j][0] = 0ull; mA2[j][1] = 0ull;
        mB2[j][0] = 0ull; mB2[j][1] = 0ull;
    }

#pragma unroll 8
    for (int k = 0; k < FF; k++) {
        float4 aA = *(const float4*)&efs_t[k][warp * 8];
        float4 aB = *(const float4*)&efs_t[k][warp * 8 + 4];
        ulonglong2 w02 = *(const ulonglong2*)&Wf[k][c0];
        ulonglong2 w12 = *(const ulonglong2*)&Wf[k][c1];
        float a[8] = {aA.x, aA.y, aA.z, aA.w, aB.x, aB.y, aB.z, aB.w};
#pragma unroll
        for (int j = 0; j < 8; j++) {
            unsigned long long ap = pack2(a[j]);
            FFMA2(mA2[j][0], ap, w02.x, mA2[j][0]);
            FFMA2(mA2[j][1], ap, w02.y, mA2[j][1]);
            FFMA2(mB2[j][0], ap, w12.x, mB2[j][0]);
            FFMA2(mB2[j][1], ap, w12.y, mB2[j][1]);
        }
    }

    // Unpack accumulators for the epilogue
    float4 mA[8], mB[8];
#pragma unroll
    for (int j = 0; j < 8; j++) {
        unpack2(mA2[j][0], mA[j].x, mA[j].y);
        unpack2(mA2[j][1], mA[j].z, mA[j].w);
        unpack2(mB2[j][0], mB[j].x, mB[j].y);
        unpack2(mB2[j][1], mB[j].z, mB[j].w);
    }

    // ---- Epilogue phase A: batched gathers + relu (no asm between loads) ----
    int sg[8], dg[8];
#pragma unroll
    for (int j = 0; j < 8; j++) {
        const int e = warp * 8 + j;
        sg[j] = nodebase + src_s[e];
        dg[j] = nodebase + tgt_s[e];
    }

#pragma unroll
    for (int j = 0; j < 8; j++) {
        float4 ps0 = *(const float4*)&g_Ps[(size_t)sg[j] * MM + c0];
        float4 pt0 = *(const float4*)&g_Pt[(size_t)dg[j] * MM + c0];
        mA[j].x = fmaxf(mA[j].x + ps0.x + pt0.x, 0.f);
        mA[j].y = fmaxf(mA[j].y + ps0.y + pt0.y, 0.f);
        mA[j].z = fmaxf(mA[j].z + ps0.z + pt0.z, 0.f);
        mA[j].w = fmaxf(mA[j].w + ps0.w + pt0.w, 0.f);
    }
#pragma unroll
    for (int j = 0; j < 8; j++) {
        float4 ps1 = *(const float4*)&g_Ps[(size_t)sg[j] * MM + c1];
        float4 pt1 = *(const float4*)&g_Pt[(size_t)dg[j] * MM + c1];
        mB[j].x = fmaxf(mB[j].x + ps1.x + pt1.x, 0.f);
        mB[j].y = fmaxf(mB[j].y + ps1.y + pt1.y, 0.f);
        mB[j].z = fmaxf(mB[j].z + ps1.z + pt1.z, 0.f);
        mB[j].w = fmaxf(mB[j].w + ps1.w + pt1.w, 0.f);
    }

    // ---- Epilogue phase B: back-to-back vector reductions ----
#pragma unroll
    for (int j = 0; j < 8; j++) {
        float* op0 = &out[(size_t)dg[j] * MM + c0];
        asm volatile("red.global.add.v4.f32 [%0], {%1, %2, %3, %4};"
                     :: "l"(op0), "f"(mA[j].x), "f"(mA[j].y), "f"(mA[j].z), "f"(mA[j].w)
                     : "memory");
    }
#pragma unroll
    for (int j = 0; j < 8; j++) {
        float* op1 = &out[(size_t)dg[j] * MM + c1];
        asm volatile("red.global.add.v4.f32 [%0], {%1, %2, %3, %4};"
                     :: "l"(op1), "f"(mB[j].x), "f"(mB[j].y), "f"(mB[j].z), "f"(mB[j].w)
                     : "memory");
    }
}

// ---------------------------------------------------------------------------
// kernel_launch — inputs identified BY ELEMENT COUNT; index dtype detected
// on device. Output f32 [4,10000,256].
// ---------------------------------------------------------------------------
extern "C" void kernel_launch(void* const* d_in, const int* in_sizes, int n_in,
                              void* d_out, int out_size) {
    const float* hidden = nullptr;
    const float* ef     = nullptr;
    const void*  srcs   = nullptr;
    const void*  tgts   = nullptr;
    const float* W      = nullptr;
    const float* bmsg   = nullptr;

    for (int i = 0; i < n_in; i++) {
        switch (in_sizes[i]) {
            case SZ_HIDDEN: hidden = (const float*)d_in[i]; break;
            case SZ_EF:     ef     = (const float*)d_in[i]; break;
            case SZ_W:      W      = (const float*)d_in[i]; break;
            case SZ_B:      bmsg   = (const float*)d_in[i]; break;
            case SZ_IDX:
                if (!srcs) srcs = d_in[i];
                else       tgts = d_in[i];
                break;
            default: break;
        }
    }
    float* out = (float*)d_out;

    // 0) detect index dtype + normalize to int32 scratch
    detect_idx_kernel<<<1, 32>>>((const int*)srcs, (const int*)tgts);
    convert_idx_kernel<<<(2 * SZ_IDX + 255) / 256, 256>>>(srcs, tgts);

    // 1) zero output (poisoned by harness)
    int n4 = out_size / 4;
    zero_kernel<<<(n4 + 255) / 256, 256>>>((float4*)out, n4);

    // 2) fused node projections: Ps = h @ W[32:160], Pt = h @ W[160:288] + b
    dim3 gA(BN / 64, MM / 64);
    node_proj_kernel<<<gA, 128>>>(hidden,
                                  W + (size_t)FF * MM,
                                  W + (size_t)(FF + HH) * MM,
                                  bmsg);

    // 3) per-edge message + scatter-add (f32x2 GEMM, phase-split epilogue)
    edge_kernel<<<NB * BLOCKS_PER_BATCH, 256>>>(ef, W, out);
}